// round 3
// baseline (speedup 1.0000x reference)
#include <cuda_runtime.h>

#define NEGF (-1000000000.0f)
#define FULLMASK 0xffffffffu

// Scratch (device globals — no allocation allowed)
__device__ float g_pot[64 * 128 * 128];   // 4 MB: label/augment-maxed span potentials
__device__ float g_goldpart[2048];        // per-block gold partial sums (32 blocks per batch)
__device__ float g_margin[64];            // per-batch relu(pred - gold)

// ---------------------------------------------------------------------------
// Kernel 1: pot + gold partials.
// One warp per span cell (b,i,j); lane l handles channel l (L=32).
// pot = max_l(v_l + aug_l) - v_0, with aug_l = (l==lab ? 0 : 1).
// gold contribution = v_lab - v_0.
// Grid: 2048 blocks (32 per batch), 256 threads (8 warps), 64 cells per warp.
// ---------------------------------------------------------------------------
__global__ void pot_kernel(const float* __restrict__ logits,
                           const int* __restrict__ labels) {
    __shared__ float potbuf[8][64];
    __shared__ float gred[8];

    int warp = threadIdx.x >> 5;
    int lane = threadIdx.x & 31;
    int b    = blockIdx.x >> 5;   // 32 blocks per batch
    int blk  = blockIdx.x & 31;

    int bcell = b * 16384;                 // cell base for this batch
    int cell0 = blk * 512 + warp * 64;     // first cell of this warp
    const float* lg = logits + (long long)bcell * 32;

    float goldacc = 0.0f;
    for (int c = 0; c < 64; ++c) {
        int cell = cell0 + c;
        int lab = labels[bcell + cell];
        if (lab < 0) lab = 0;              // jnp.maximum(labels, 0)
        float v = lg[cell * 32 + lane];
        float t = (lane == lab) ? v : (v + 1.0f);
        #pragma unroll
        for (int off = 16; off; off >>= 1)
            t = fmaxf(t, __shfl_xor_sync(FULLMASK, t, off));
        float v0 = __shfl_sync(FULLMASK, v, 0);
        float vl = __shfl_sync(FULLMASK, v, lab);
        goldacc += vl - v0;                // same value in all lanes
        if (lane == 0) potbuf[warp][c] = t - v0;
    }
    __syncwarp();
    // coalesced pot store: each warp writes its 64 contiguous values
    {
        float* dst = g_pot + bcell + cell0;
        dst[lane]      = potbuf[warp][lane];
        dst[lane + 32] = potbuf[warp][lane + 32];
    }
    if (lane == 0) gred[warp] = goldacc;
    __syncthreads();
    if (threadIdx.x == 0) {
        float s = 0.0f;
        #pragma unroll
        for (int w = 0; w < 8; ++w) s += gred[w];
        g_goldpart[blockIdx.x] = s;        // index == b*32 + blk
    }
}

// ---------------------------------------------------------------------------
// Kernel 2: CKY max-plus inside pass. One CTA per batch, 128 threads.
// SMEM: betaS[i][w]    = best score of span [i, i+w]        (start-indexed)
//       betaE[e][127-w] = best score of span [e-w, e]       (end-indexed)
// Recurrence (thread i, width w):
//   betaS[i][w] = pot[i][i+w] + max_{k<w} betaS[i][k] + betaE[i+w][128-w+k]
// Both operands contiguous in k, row stride 129 (odd) -> conflict-free.
// ---------------------------------------------------------------------------
extern __shared__ float cky_smem[];

__global__ void cky_kernel(const float* __restrict__ logits,
                           const int* __restrict__ labels) {
    float* betaS = cky_smem;                    // 128*129
    float* betaE = cky_smem + 128 * 129;        // 128*129
    float* potS  = cky_smem + 2 * 128 * 129;    // 128*129
    __shared__ float sh_potfix;

    int b = blockIdx.x;
    int t = threadIdx.x;
    int bcell = b * 16384;

    // length: count labels[b,0,j] != -100 (all 128 threads participate)
    int labt = labels[bcell + t];
    int len = __syncthreads_count(labt != -100);

    // preload pot rows into SMEM (coalesced, conflict-free writes)
    for (int idx = t; idx < 16384; idx += 128) {
        potS[(idx >> 7) * 129 + (idx & 127)] = g_pot[bcell + idx];
    }

    // recompute the augmented special cell (b, 0, len-1): channel 0 gets -1e9
    if (t < 32) {
        int j = len - 1;
        int lab = labels[bcell + j];
        if (lab < 0) lab = 0;
        float v = logits[(long long)(bcell + j) * 32 + t];
        float x = (t == lab) ? v : (v + 1.0f);
        if (t == 0) x += NEGF;
        #pragma unroll
        for (int off = 16; off; off >>= 1)
            x = fmaxf(x, __shfl_xor_sync(FULLMASK, x, off));
        float v0 = __shfl_sync(FULLMASK, v, 0);
        if (t == 0) sh_potfix = x - v0;
    }
    __syncthreads();
    if (t == 0) potS[len - 1] = sh_potfix;      // row 0, col len-1
    __syncthreads();

    // width-0 init (diagonal terms)
    {
        float d = potS[t * 129 + t];
        betaS[t * 129]       = d;
        betaE[t * 129 + 127] = d;
    }

    for (int w = 1; w < 128; ++w) {
        __syncthreads();                        // writes of step w-1 visible
        int i = t;
        if (i < 128 - w) {
            const float* A = betaS + i * 129;                   // [i][k], k < w
            const float* E = betaE + (i + w) * 129 + (128 - w); // [i+w][128-w+k]
            float best = NEGF;
            #pragma unroll 4
            for (int k = 0; k < w; ++k)
                best = fmaxf(best, A[k] + E[k]);
            float v = best + potS[i * 129 + i + w];
            // writes at step w are disjoint from all reads at step w
            betaS[i * 129 + w]             = v;
            betaE[(i + w) * 129 + 127 - w] = v;
        }
    }
    __syncthreads();

    // deterministic gold reduction: 32 per-block partials for this batch
    if (t < 32) {
        float g = g_goldpart[b * 32 + t];
        #pragma unroll
        for (int off = 16; off; off >>= 1)
            g += __shfl_xor_sync(FULLMASK, g, off);
        if (t == 0) {
            float pred = betaS[len - 1];        // betaS[0][len-1]
            g_margin[b] = fmaxf(pred - g, 0.0f);
        }
    }
}

// ---------------------------------------------------------------------------
// Kernel 3: mean over batches.
// ---------------------------------------------------------------------------
__global__ void mean_kernel(float* __restrict__ out) {
    int t = threadIdx.x;                        // 32 threads
    float v = g_margin[t] + g_margin[t + 32];
    #pragma unroll
    for (int off = 16; off; off >>= 1)
        v += __shfl_xor_sync(FULLMASK, v, off);
    if (t == 0) out[0] = v * (1.0f / 64.0f);
}

// ---------------------------------------------------------------------------
extern "C" void kernel_launch(void* const* d_in, const int* in_sizes, int n_in,
                              void* d_out, int out_size) {
    const float* logits = (const float*)d_in[0];   // [64,128,128,32] f32
    const int* labels   = (const int*)d_in[1];     // [64,128,128] int32
    float* out = (float*)d_out;

    (void)in_sizes; (void)n_in; (void)out_size;

    const int CKY_SMEM = 3 * 128 * 129 * (int)sizeof(float); // 198144 B
    cudaFuncSetAttribute(cky_kernel,
                         cudaFuncAttributeMaxDynamicSharedMemorySize, CKY_SMEM);

    pot_kernel<<<2048, 256>>>(logits, labels);
    cky_kernel<<<64, 128, CKY_SMEM>>>(logits, labels);
    mean_kernel<<<1, 32>>>(out);
}